// round 11
// baseline (speedup 1.0000x reference)
#include <cuda_runtime.h>

#define BB 8
#define CC 512
#define TT 8192
#define OPT 32              // outputs per thread
#define NT 128              // threads per block
#define CHUNK (NT * OPT)    // 4096 outputs per block
#define NCHUNK (TT / CHUNK) // 2 blocks per (b,c) row
#define NU (OPT + 5)        // 37 z-pairs per thread

__global__ __launch_bounds__(NT) void aa_fused_kernel(
    const float* __restrict__ x,
    const float* __restrict__ alpha,
    const float* __restrict__ beta,
    const float* __restrict__ fu,
    const float* __restrict__ fd,
    float* __restrict__ out)
{
    __shared__ float s_g0[6], s_F[6];
    __shared__ float s_a, s_ib;

    const int tid = threadIdx.x;
    const int bid = blockIdx.x;
    const int row = bid >> 1;       // NCHUNK == 2
    const int chunk = bid & 1;
    const int c = row & (CC - 1);

    // g0[r] = 2*fu[10-2r] (odd-n phase). Even-n phase g1[r] == g0[5-r]
    // (kaiser filter symmetric: fu[i] == fu[11-i] bit-exact).
    // Down filter: fd[2d] == F[d], fd[2d+1] == F[5-d], F[d] = fd[map[d]].
    if (tid < 6) {
        s_g0[tid] = 2.0f * fu[10 - 2 * tid];
    } else if (tid < 12) {
        const int d = tid - 6;
        const int map[6] = {0, 2, 4, 5, 3, 1};
        s_F[d] = fd[map[d]];
    } else if (tid == 12) {
        s_a = expf(alpha[c]);
    } else if (tid == 13) {
        s_ib = 1.0f / (expf(beta[c]) + 1e-9f);
    }
    __syncthreads();

    float g0r[6], F[6];
    #pragma unroll
    for (int r = 0; r < 6; r++) { g0r[r] = s_g0[r]; F[r] = s_F[r]; }
    const float a  = s_a;
    const float ib = s_ib;

    const float* xrow = x + (size_t)row * TT;
    float* orow = out + (size_t)row * TT;
    const int tb = chunk * CHUNK + tid * OPT;

    const bool elo = (tb == 0);
    const bool ehi = (tb == TT - OPT);   // 8160

    // Rolling x window: logical xq[j] = x[tb-8+j] lives in xr[j & 15].
    // Live span at iteration u is j in [3+u, 11+u] (9 slots <= 16).
    float xr[16];
    #pragma unroll
    for (int v = 0; v < 4; v++) {
        const int b = tb - 8 + 4 * v;
        const int bc = min(max(b, 0), TT - 4);
        float4 q = *(const float4*)(xrow + bc);
        if (b < 0) { q.y = q.x; q.z = q.x; q.w = q.x; }   // replicate-left (elo only)
        xr[4 * v + 0] = q.x; xr[4 * v + 1] = q.y;
        xr[4 * v + 2] = q.z; xr[4 * v + 3] = q.w;
    }

    // zlo = z at upsampled n = 0 (row-left clamp target); xr[8..10] = x[tb..tb+2]
    float zlo;
    {
        const float x0 = xr[8], x1 = xr[9], x2 = xr[10];
        float accl = x0 * (g0r[5] + g0r[4] + g0r[3] + g0r[2])
                   + g0r[1] * x1 + g0r[0] * x2;
        const float sl = __sinf(accl * a);
        zlo = fmaf(sl * sl, ib, accl);
    }

    float o[OPT];
    float zh = 0.0f;

    // Stream pairs u = 0..36: z0 = z[s=2u] (n odd, taps g0),
    // z1 = z[s=2u+1] (n even, taps g0 reversed); window xq[3+u .. 8+u].
    // n = 2*tb - 5 + s. Scatter: o[u-d] += F[d]*z0 + F[5-d]*z1, d = 0..5.
    #pragma unroll
    for (int u = 0; u < NU; u++) {
        // refill ring: at u = 8,12,...,36 load xq[u+8 .. u+11] = x[tb+u .. tb+u+3]
        if (u >= 8 && (u & 3) == 0) {
            const int b = tb + u;
            const int bc = min(b, TT - 4);
            float4 q = *(const float4*)(xrow + bc);
            if (b > TT - 4) { q.x = q.w; q.y = q.w; q.z = q.w; }  // replicate-right (ehi only)
            xr[(u + 8)  & 15] = q.x; xr[(u + 9)  & 15] = q.y;
            xr[(u + 10) & 15] = q.z; xr[(u + 11) & 15] = q.w;
        }

        float acc0 = g0r[0] * xr[(3 + u) & 15];
        float acc1 = g0r[5] * xr[(3 + u) & 15];
        #pragma unroll
        for (int r = 1; r < 6; r++) {
            const float xv = xr[(3 + u + r) & 15];
            acc0 = fmaf(g0r[r],     xv, acc0);
            acc1 = fmaf(g0r[5 - r], xv, acc1);
        }
        const float s0 = __sinf(acc0 * a);
        const float s1 = __sinf(acc1 * a);
        float z0 = fmaf(s0 * s0, ib, acc0);
        float z1 = fmaf(s1 * s1, ib, acc1);

        // row-left clamp: s < 5 (n < 0) -> z(n=0)
        if (u == 0 || u == 1) { z0 = elo ? zlo : z0; z1 = elo ? zlo : z1; }
        if (u == 2)           { z0 = elo ? zlo : z0; }
        // row-right clamp (tb = 8160): s > 68 (n > 2T-1) -> z(s=68) = z(n=2T-1)
        if (u == 34) { zh = z0; z1 = ehi ? zh : z1; }
        if (u >= 35) { z0 = ehi ? zh : z0; z1 = ehi ? zh : z1; }

        #pragma unroll
        for (int d = 0; d < 6; d++) {
            const int i = u - d;
            if (i >= 0 && i < OPT) {
                if (d == 0) o[i] = fmaf(F[0], z0, F[5] * z1);
                else        o[i] = fmaf(F[d], z0, fmaf(F[5 - d], z1, o[i]));
            }
        }

        // store group g = (u-8)/4 when its last contribution (u = 4g+8) lands
        if (u >= 8 && (u & 3) == 0) {
            const int g = (u - 8);   // = 4g_base
            *(float4*)(orow + tb + g - 8 + 8) ;  // (no-op expression avoided below)
        }
        if (u == 8)  *(float4*)(orow + tb +  0) = make_float4(o[0],  o[1],  o[2],  o[3]);
        if (u == 12) *(float4*)(orow + tb +  4) = make_float4(o[4],  o[5],  o[6],  o[7]);
        if (u == 16) *(float4*)(orow + tb +  8) = make_float4(o[8],  o[9],  o[10], o[11]);
        if (u == 20) *(float4*)(orow + tb + 12) = make_float4(o[12], o[13], o[14], o[15]);
        if (u == 24) *(float4*)(orow + tb + 16) = make_float4(o[16], o[17], o[18], o[19]);
        if (u == 28) *(float4*)(orow + tb + 20) = make_float4(o[20], o[21], o[22], o[23]);
        if (u == 32) *(float4*)(orow + tb + 24) = make_float4(o[24], o[25], o[26], o[27]);
        if (u == 36) *(float4*)(orow + tb + 28) = make_float4(o[28], o[29], o[30], o[31]);
    }
}

extern "C" void kernel_launch(void* const* d_in, const int* in_sizes, int n_in,
                              void* d_out, int out_size)
{
    const float* x     = (const float*)d_in[0];
    const float* alpha = (const float*)d_in[1];
    const float* beta  = (const float*)d_in[2];
    const float* fu    = (const float*)d_in[3];
    const float* fd    = (const float*)d_in[4];
    float* out = (float*)d_out;

    const int grid = BB * CC * NCHUNK; // 8192
    aa_fused_kernel<<<grid, NT>>>(x, alpha, beta, fu, fd, out);
}

// round 12
// speedup vs baseline: 1.1358x; 1.1358x over previous
#include <cuda_runtime.h>

#define BB 8
#define CC 512
#define TT 8192
#define OPT 32              // outputs per thread
#define NT 128              // threads per block
#define CHUNK (NT * OPT)    // 4096 outputs per block
#define NCHUNK (TT / CHUNK) // 2 blocks per (b,c) row
#define NU (OPT + 5)        // 37 z-pairs per thread

__global__ __launch_bounds__(NT, 8) void aa_fused_kernel(
    const float* __restrict__ x,
    const float* __restrict__ alpha,
    const float* __restrict__ beta,
    const float* __restrict__ fu,
    const float* __restrict__ fd,
    float* __restrict__ out)
{
    __shared__ float s_g0[6], s_F[6];
    __shared__ float s_a, s_ib;

    const int tid = threadIdx.x;
    const int bid = blockIdx.x;
    const int row = bid >> 1;       // NCHUNK == 2
    const int chunk = bid & 1;
    const int c = row & (CC - 1);

    // g0[r] = 2*fu[10-2r] (odd-n phase). Even-n phase g1[r] == g0[5-r]
    // (kaiser filter symmetric: fu[i] == fu[11-i] bit-exact).
    // Down filter: fd[2d] == F[d], fd[2d+1] == F[5-d], F[d] = fd[map[d]].
    if (tid < 6) {
        s_g0[tid] = 2.0f * fu[10 - 2 * tid];
    } else if (tid < 12) {
        const int d = tid - 6;
        const int map[6] = {0, 2, 4, 5, 3, 1};
        s_F[d] = fd[map[d]];
    } else if (tid == 12) {
        s_a = expf(alpha[c]);
    } else if (tid == 13) {
        s_ib = 1.0f / (expf(beta[c]) + 1e-9f);
    }
    __syncthreads();

    float g0r[6], F[6];
    #pragma unroll
    for (int r = 0; r < 6; r++) { g0r[r] = s_g0[r]; F[r] = s_F[r]; }
    const float a  = s_a;
    const float ib = s_ib;

    const float* xrow = x + (size_t)row * TT;
    float* orow = out + (size_t)row * TT;
    const int tb = chunk * CHUNK + tid * OPT;

    const bool elo = (tb == 0);
    const bool ehi = (tb == TT - OPT);   // 8160

    // Rolling x window: logical xq[j] = x[tb-8+j] lives in xr[j & 15].
    // Live span at iteration u is j in [3+u, 11+u] (9 slots <= 16).
    float xr[16];
    #pragma unroll
    for (int v = 0; v < 4; v++) {
        const int b = tb - 8 + 4 * v;
        const int bc = min(max(b, 0), TT - 4);
        float4 q = *(const float4*)(xrow + bc);
        if (b < 0) { q.y = q.x; q.z = q.x; q.w = q.x; }   // replicate-left (elo only)
        xr[4 * v + 0] = q.x; xr[4 * v + 1] = q.y;
        xr[4 * v + 2] = q.z; xr[4 * v + 3] = q.w;
    }

    // zlo = z at upsampled n = 0 (row-left clamp target); xr[8..10] = x[tb..tb+2]
    float zlo;
    {
        const float x0 = xr[8], x1 = xr[9], x2 = xr[10];
        float accl = x0 * (g0r[5] + g0r[4] + g0r[3] + g0r[2])
                   + g0r[1] * x1 + g0r[0] * x2;
        const float sl = __sinf(accl * a);
        zlo = fmaf(sl * sl, ib, accl);
    }

    float o[OPT];
    float zh = 0.0f;

    // Stream pairs u = 0..36: z0 = z[s=2u] (n odd, taps g0),
    // z1 = z[s=2u+1] (n even, taps g0 reversed); window xq[3+u .. 8+u].
    // n = 2*tb - 5 + s. Scatter: o[u-d] += F[d]*z0 + F[5-d]*z1, d = 0..5.
    #pragma unroll
    for (int u = 0; u < NU; u++) {
        // refill ring: at u = 8,12,...,36 load xq[u+8 .. u+11] = x[tb+u .. tb+u+3]
        if (u >= 8 && (u & 3) == 0) {
            const int b = tb + u;
            const int bc = min(b, TT - 4);
            float4 q = *(const float4*)(xrow + bc);
            if (b > TT - 4) { q.x = q.w; q.y = q.w; q.z = q.w; }  // replicate-right (ehi only)
            xr[(u + 8)  & 15] = q.x; xr[(u + 9)  & 15] = q.y;
            xr[(u + 10) & 15] = q.z; xr[(u + 11) & 15] = q.w;
        }

        float acc0 = g0r[0] * xr[(3 + u) & 15];
        float acc1 = g0r[5] * xr[(3 + u) & 15];
        #pragma unroll
        for (int r = 1; r < 6; r++) {
            const float xv = xr[(3 + u + r) & 15];
            acc0 = fmaf(g0r[r],     xv, acc0);
            acc1 = fmaf(g0r[5 - r], xv, acc1);
        }
        const float s0 = __sinf(acc0 * a);
        const float s1 = __sinf(acc1 * a);
        float z0 = fmaf(s0 * s0, ib, acc0);
        float z1 = fmaf(s1 * s1, ib, acc1);

        // row-left clamp: s < 5 (n < 0) -> z(n=0)
        if (u == 0 || u == 1) { z0 = elo ? zlo : z0; z1 = elo ? zlo : z1; }
        if (u == 2)           { z0 = elo ? zlo : z0; }
        // row-right clamp (tb = 8160): s > 68 (n > 2T-1) -> z(s=68) = z(n=2T-1)
        if (u == 34) { zh = z0; z1 = ehi ? zh : z1; }
        if (u >= 35) { z0 = ehi ? zh : z0; z1 = ehi ? zh : z1; }

        #pragma unroll
        for (int d = 0; d < 6; d++) {
            const int i = u - d;
            if (i >= 0 && i < OPT) {
                if (d == 0) o[i] = fmaf(F[0], z0, F[5] * z1);
                else        o[i] = fmaf(F[d], z0, fmaf(F[5 - d], z1, o[i]));
            }
        }

        // store each group of 4 outputs as soon as its last contribution lands
        if (u == 8)  *(float4*)(orow + tb +  0) = make_float4(o[0],  o[1],  o[2],  o[3]);
        if (u == 12) *(float4*)(orow + tb +  4) = make_float4(o[4],  o[5],  o[6],  o[7]);
        if (u == 16) *(float4*)(orow + tb +  8) = make_float4(o[8],  o[9],  o[10], o[11]);
        if (u == 20) *(float4*)(orow + tb + 12) = make_float4(o[12], o[13], o[14], o[15]);
        if (u == 24) *(float4*)(orow + tb + 16) = make_float4(o[16], o[17], o[18], o[19]);
        if (u == 28) *(float4*)(orow + tb + 20) = make_float4(o[20], o[21], o[22], o[23]);
        if (u == 32) *(float4*)(orow + tb + 24) = make_float4(o[24], o[25], o[26], o[27]);
        if (u == 36) *(float4*)(orow + tb + 28) = make_float4(o[28], o[29], o[30], o[31]);
    }
}

extern "C" void kernel_launch(void* const* d_in, const int* in_sizes, int n_in,
                              void* d_out, int out_size)
{
    const float* x     = (const float*)d_in[0];
    const float* alpha = (const float*)d_in[1];
    const float* beta  = (const float*)d_in[2];
    const float* fu    = (const float*)d_in[3];
    const float* fd    = (const float*)d_in[4];
    float* out = (float*)d_out;

    const int grid = BB * CC * NCHUNK; // 8192
    aa_fused_kernel<<<grid, NT>>>(x, alpha, beta, fu, fd, out);
}